// round 1
// baseline (speedup 1.0000x reference)
#include <cuda_runtime.h>

#define N_NODES 100000
#define N_EDGES 1600000
#define F 128

// ---------------- scratch (static device allocations; no cudaMalloc) --------
__device__ int g_is64;
__device__ __align__(16) int g_off[N_NODES + 1];
__device__ __align__(16) int g_cur[N_NODES];
__device__ __align__(16) int g_csr[N_EDGES];
__device__ __align__(16) float g_t[(size_t)N_NODES * F]; // x + agg
__device__ __align__(16) float g_m[(size_t)N_NODES * F]; // relu(t@W1+b1)
__device__ __align__(16) float g_h[(size_t)N_NODES * F]; // layer output

// ---------------- edge dtype detection (int64 vs int32) ---------------------
__global__ void k_detect(const unsigned int* __restrict__ ei32) {
    __shared__ int any;
    if (threadIdx.x == 0) any = 0;
    __syncthreads();
    int local = 0;
    // If data is int64 (LE), every odd 32-bit word is a high word == 0
    // (values in [0, 100000)). If int32, these are real edge ids, and the
    // chance all 65536 sampled are zero is nil.
    for (int i = threadIdx.x; i < 65536; i += blockDim.x)
        if (ei32[2 * i + 1] != 0u) local = 1;
    if (local) any = 1;
    __syncthreads();
    if (threadIdx.x == 0) g_is64 = (any == 0) ? 1 : 0;
}

__device__ __forceinline__ int edge_val(const void* ei, int idx) {
    if (g_is64) return (int)(((const long long*)ei)[idx]);
    return ((const int*)ei)[idx];
}

// ---------------- CSR build --------------------------------------------------
__global__ void k_zero_off() {
    int i = blockIdx.x * blockDim.x + threadIdx.x;
    if (i <= N_NODES) g_off[i] = 0;
}

__global__ void k_count(const void* __restrict__ ei) {
    int e = blockIdx.x * blockDim.x + threadIdx.x;
    if (e < N_EDGES) {
        int d = edge_val(ei, N_EDGES + e);
        atomicAdd(&g_off[d + 1], 1);
    }
}

// single-block inclusive scan over g_off[0..N_NODES] (off[0] stays 0)
__global__ void k_scan() {
    __shared__ int s[1024];
    __shared__ int s_carry;
    int tid = threadIdx.x;
    if (tid == 0) s_carry = 0;
    __syncthreads();
    for (int base = 0; base <= N_NODES; base += 1024) {
        int i = base + tid;
        int v = (i <= N_NODES) ? g_off[i] : 0;
        s[tid] = v;
        __syncthreads();
        #pragma unroll
        for (int d = 1; d < 1024; d <<= 1) {
            int t = (tid >= d) ? s[tid - d] : 0;
            __syncthreads();
            s[tid] += t;
            __syncthreads();
        }
        int val = s[tid] + s_carry;
        if (i <= N_NODES) {
            g_off[i] = val;
            if (i < N_NODES) g_cur[i] = val;
        }
        __syncthreads();
        if (tid == 1023) s_carry = val;
        __syncthreads();
    }
}

__global__ void k_fill(const void* __restrict__ ei) {
    int e = blockIdx.x * blockDim.x + threadIdx.x;
    if (e < N_EDGES) {
        int s = edge_val(ei, e);
        int d = edge_val(ei, N_EDGES + e);
        int p = atomicAdd(&g_cur[d], 1);
        g_csr[p] = s;
    }
}

// ---------------- aggregation: g_t[i] = in[i] + sum_{j->i} in[j] -------------
__global__ void k_agg(const float* __restrict__ x, int layer) {
    const float* in = (layer == 0) ? x : (const float*)g_h;
    int w = (blockIdx.x * blockDim.x + threadIdx.x) >> 5;
    if (w >= N_NODES) return;
    int lane = threadIdx.x & 31;
    const float4* xin = (const float4*)in;
    float4 acc = xin[(size_t)w * 32 + lane];
    int e = g_off[w];
    int end = g_off[w + 1];
    for (; e + 4 <= end; e += 4) {
        int s0 = g_csr[e], s1 = g_csr[e + 1], s2 = g_csr[e + 2], s3 = g_csr[e + 3];
        float4 v0 = xin[(size_t)s0 * 32 + lane];
        float4 v1 = xin[(size_t)s1 * 32 + lane];
        float4 v2 = xin[(size_t)s2 * 32 + lane];
        float4 v3 = xin[(size_t)s3 * 32 + lane];
        acc.x += (v0.x + v1.x) + (v2.x + v3.x);
        acc.y += (v0.y + v1.y) + (v2.y + v3.y);
        acc.z += (v0.z + v1.z) + (v2.z + v3.z);
        acc.w += (v0.w + v1.w) + (v2.w + v3.w);
    }
    for (; e < end; e++) {
        int s0 = g_csr[e];
        float4 v0 = xin[(size_t)s0 * 32 + lane];
        acc.x += v0.x; acc.y += v0.y; acc.z += v0.z; acc.w += v0.w;
    }
    ((float4*)g_t)[(size_t)w * 32 + lane] = acc;
}

// ---------------- GEMM: out[n][j] = act(in[n,:] . W[:,j] + b[j]) -------------
// 256 threads, 64 nodes/block, thread tile = 8 nodes x 4 outputs.
// src_sel: 0 -> g_t, 1 -> g_m ; dst_sel: 0 -> g_m, 1 -> g_h
__global__ void k_gemm(const float* __restrict__ W, const float* __restrict__ b,
                       int src_sel, int dst_sel, int do_relu) {
    extern __shared__ float smem[];
    float* sW = smem;            // 128*128 floats
    float* sT = smem + F * F;    // 64*128 floats

    const float* in = src_sel ? (const float*)g_m : (const float*)g_t;
    float* out = dst_sel ? (float*)g_h : (float*)g_m;

    int tid = threadIdx.x;
    int nbase = blockIdx.x * 64;

    const float4* W4 = (const float4*)W;
    float4* sW4 = (float4*)sW;
    #pragma unroll
    for (int i = 0; i < 16; i++) sW4[tid + i * 256] = W4[tid + i * 256];

    const float4* T4 = (const float4*)in;
    float4* sT4 = (float4*)sT;
    #pragma unroll
    for (int i = 0; i < 8; i++) {
        int idx = tid + i * 256;          // float4 index in 64x32 tile
        int n = nbase + (idx >> 5);
        sT4[idx] = (n < N_NODES) ? T4[(size_t)n * 32 + (idx & 31)]
                                 : make_float4(0.f, 0.f, 0.f, 0.f);
    }
    __syncthreads();

    int tx = tid & 31;   // output group: cols tx*4 .. tx*4+3
    int ty = tid >> 5;   // node group: rows ty*8 .. ty*8+7
    float acc[8][4];
    #pragma unroll
    for (int i = 0; i < 8; i++)
        #pragma unroll
        for (int j = 0; j < 4; j++) acc[i][j] = 0.f;

    const float* tb = sT + (ty * 8) * F;
    #pragma unroll 2
    for (int k = 0; k < F; k++) {
        float4 wv = *(const float4*)(sW + k * F + tx * 4);
        #pragma unroll
        for (int i = 0; i < 8; i++) {
            float tv = tb[i * F + k];
            acc[i][0] += tv * wv.x;
            acc[i][1] += tv * wv.y;
            acc[i][2] += tv * wv.z;
            acc[i][3] += tv * wv.w;
        }
    }

    float4 bv = *(const float4*)(b + tx * 4);
    #pragma unroll
    for (int i = 0; i < 8; i++) {
        int n = nbase + ty * 8 + i;
        if (n < N_NODES) {
            float4 o;
            o.x = acc[i][0] + bv.x;
            o.y = acc[i][1] + bv.y;
            o.z = acc[i][2] + bv.z;
            o.w = acc[i][3] + bv.w;
            if (do_relu) {
                o.x = fmaxf(o.x, 0.f); o.y = fmaxf(o.y, 0.f);
                o.z = fmaxf(o.z, 0.f); o.w = fmaxf(o.w, 0.f);
            }
            *(float4*)(out + (size_t)n * F + tx * 4) = o;
        }
    }
}

// ---------------- final 128 -> 1 dot per node --------------------------------
__global__ void k_dot(const float* __restrict__ w, const float* __restrict__ b,
                      float* __restrict__ out) {
    __shared__ __align__(16) float sw[F];
    if (threadIdx.x < F) sw[threadIdx.x] = w[threadIdx.x];
    __syncthreads();
    int node = (blockIdx.x * blockDim.x + threadIdx.x) >> 5;
    if (node >= N_NODES) return;
    int lane = threadIdx.x & 31;
    float4 v = ((const float4*)g_m)[(size_t)node * 32 + lane];
    float4 wv = ((const float4*)sw)[lane];
    float s = v.x * wv.x + v.y * wv.y + v.z * wv.z + v.w * wv.w;
    #pragma unroll
    for (int o = 16; o; o >>= 1) s += __shfl_down_sync(0xffffffffu, s, o);
    if (lane == 0) out[node] = s + b[0];
}

// ---------------- launch ------------------------------------------------------
extern "C" void kernel_launch(void* const* d_in, const int* in_sizes, int n_in,
                              void* d_out, int out_size) {
    const float* x = (const float*)d_in[0];
    const void* ei = d_in[1];
    const float* w11 = (const float*)d_in[2];
    const float* b11 = (const float*)d_in[3];
    const float* w12 = (const float*)d_in[4];
    const float* b12 = (const float*)d_in[5];
    const float* w21 = (const float*)d_in[6];
    const float* b21 = (const float*)d_in[7];
    const float* w22 = (const float*)d_in[8];
    const float* b22 = (const float*)d_in[9];
    const float* w31 = (const float*)d_in[10];
    const float* b31 = (const float*)d_in[11];
    const float* w32 = (const float*)d_in[12];
    const float* b32 = (const float*)d_in[13];
    float* out = (float*)d_out;

    static int smem_set = 0;
    const int SMEM = (F * F + 64 * F) * (int)sizeof(float); // 96 KB
    if (!smem_set) {
        cudaFuncSetAttribute(k_gemm, cudaFuncAttributeMaxDynamicSharedMemorySize, SMEM);
        smem_set = 1;
    }

    // CSR build (depends only on edge_index)
    k_detect<<<1, 1024>>>((const unsigned int*)ei);
    k_zero_off<<<(N_NODES + 256) / 256, 256>>>();
    k_count<<<(N_EDGES + 255) / 256, 256>>>(ei);
    k_scan<<<1, 1024>>>();
    k_fill<<<(N_EDGES + 255) / 256, 256>>>(ei);

    const int AGG_BLOCKS = (N_NODES * 32 + 255) / 256;   // warp per node
    const int GEMM_BLOCKS = (N_NODES + 63) / 64;

    const float* W1s[3] = {w11, w21, w31};
    const float* B1s[3] = {b11, b21, b31};
    const float* W2s[2] = {w12, w22};
    const float* B2s[2] = {b12, b22};

    for (int l = 0; l < 3; l++) {
        k_agg<<<AGG_BLOCKS, 256>>>(x, l);                          // -> g_t
        k_gemm<<<GEMM_BLOCKS, 256, SMEM>>>(W1s[l], B1s[l], 0, 0, 1); // g_t -> g_m (relu)
        if (l < 2) {
            k_gemm<<<GEMM_BLOCKS, 256, SMEM>>>(W2s[l], B2s[l], 1, 1, 0); // g_m -> g_h
        } else {
            k_dot<<<AGG_BLOCKS, 256>>>(w32, b32, out);             // g_m -> out
        }
    }
}

// round 2
// speedup vs baseline: 1.0593x; 1.0593x over previous
#include <cuda_runtime.h>

#define N_NODES 100000
#define N_EDGES 1600000
#define F 128
#define SCAN_B 196   // ceil(100001 / 512)

// ---------------- scratch (static device allocations; no cudaMalloc) --------
__device__ int g_is64;
__device__ __align__(16) int g_off[N_NODES + 1];
__device__ __align__(16) int g_cur[N_NODES];
__device__ __align__(16) int g_csr[N_EDGES];
__device__ __align__(16) int g_part[SCAN_B];
__device__ __align__(16) float g_t[(size_t)N_NODES * F]; // x + agg
__device__ __align__(16) float g_m[(size_t)N_NODES * F]; // relu(t@W1+b1)
__device__ __align__(16) float g_h[(size_t)N_NODES * F]; // layer output

// ---------------- f32x2 helpers ----------------------------------------------
__device__ __forceinline__ unsigned long long pk2(float a, float b) {
    unsigned long long r;
    asm("mov.b64 %0, {%1, %2};" : "=l"(r) : "f"(a), "f"(b));
    return r;
}
__device__ __forceinline__ void fma2(unsigned long long& d,
                                     unsigned long long a, unsigned long long b) {
    asm("fma.rn.f32x2 %0, %1, %2, %0;" : "+l"(d) : "l"(a), "l"(b));
}
__device__ __forceinline__ float fold2(unsigned long long v) {
    float lo, hi;
    asm("mov.b64 {%0, %1}, %2;" : "=f"(lo), "=f"(hi) : "l"(v));
    return lo + hi;
}

// ---------------- edge dtype detection (int64 vs int32) ---------------------
__global__ void k_detect(const unsigned int* __restrict__ ei32) {
    __shared__ int any;
    if (threadIdx.x == 0) any = 0;
    __syncthreads();
    int local = 0;
    for (int i = threadIdx.x; i < 65536; i += blockDim.x)
        if (ei32[2 * i + 1] != 0u) local = 1;
    if (local) any = 1;
    __syncthreads();
    if (threadIdx.x == 0) g_is64 = (any == 0) ? 1 : 0;
}

__device__ __forceinline__ int edge_val(const void* ei, int idx) {
    if (g_is64) return (int)(((const long long*)ei)[idx]);
    return ((const int*)ei)[idx];
}

// ---------------- CSR build --------------------------------------------------
__global__ void k_zero_off() {
    int i = blockIdx.x * blockDim.x + threadIdx.x;
    if (i <= N_NODES) g_off[i] = 0;
}

__global__ void k_count(const void* __restrict__ ei) {
    int e = blockIdx.x * blockDim.x + threadIdx.x;
    if (e < N_EDGES) {
        int d = edge_val(ei, N_EDGES + e);
        atomicAdd(&g_off[d + 1], 1);
    }
}

// multi-block scan, pass 1: per-block inclusive scan of 512 elems + block total
__global__ void k_scan1() {
    __shared__ int wsum[16];
    int tid = threadIdx.x;
    int i = blockIdx.x * 512 + tid;
    int lane = tid & 31, w = tid >> 5;
    int s = (i <= N_NODES) ? g_off[i] : 0;
    #pragma unroll
    for (int o = 1; o < 32; o <<= 1) {
        int t = __shfl_up_sync(0xffffffffu, s, o);
        if (lane >= o) s += t;
    }
    if (lane == 31) wsum[w] = s;
    __syncthreads();
    if (w == 0) {
        int ws = (lane < 16) ? wsum[lane] : 0;
        #pragma unroll
        for (int o = 1; o < 16; o <<= 1) {
            int t = __shfl_up_sync(0xffffffffu, ws, o);
            if (lane >= o) ws += t;
        }
        if (lane < 16) wsum[lane] = ws;
    }
    __syncthreads();
    int incl = s + (w > 0 ? wsum[w - 1] : 0);
    if (i <= N_NODES) g_off[i] = incl;
    if (tid == 511) g_part[blockIdx.x] = incl;
}

// pass 2: single block scans the SCAN_B block totals
__global__ void k_scan2() {
    __shared__ int wsum[8];
    int tid = threadIdx.x;
    int lane = tid & 31, w = tid >> 5;
    int s = (tid < SCAN_B) ? g_part[tid] : 0;
    #pragma unroll
    for (int o = 1; o < 32; o <<= 1) {
        int t = __shfl_up_sync(0xffffffffu, s, o);
        if (lane >= o) s += t;
    }
    if (lane == 31) wsum[w] = s;
    __syncthreads();
    if (w == 0) {
        int ws = (lane < 8) ? wsum[lane] : 0;
        #pragma unroll
        for (int o = 1; o < 8; o <<= 1) {
            int t = __shfl_up_sync(0xffffffffu, ws, o);
            if (lane >= o) ws += t;
        }
        if (lane < 8) wsum[lane] = ws;
    }
    __syncthreads();
    int incl = s + (w > 0 ? wsum[w - 1] : 0);
    if (tid < SCAN_B) g_part[tid] = incl;
}

// pass 3: add block prefix, produce final offsets + g_cur
__global__ void k_scan3() {
    int tid = threadIdx.x;
    int b = blockIdx.x;
    int i = b * 512 + tid;
    if (i <= N_NODES) {
        int v = g_off[i] + (b > 0 ? g_part[b - 1] : 0);
        g_off[i] = v;
        if (i < N_NODES) g_cur[i] = v;
    }
}

__global__ void k_fill(const void* __restrict__ ei) {
    int e = blockIdx.x * blockDim.x + threadIdx.x;
    if (e < N_EDGES) {
        int s = edge_val(ei, e);
        int d = edge_val(ei, N_EDGES + e);
        int p = atomicAdd(&g_cur[d], 1);
        g_csr[p] = s;
    }
}

// ---------------- aggregation: g_t[i] = in[i] + sum_{j->i} in[j] -------------
__global__ void k_agg(const float* __restrict__ x, int layer) {
    const float* in = (layer == 0) ? x : (const float*)g_h;
    int w = (blockIdx.x * blockDim.x + threadIdx.x) >> 5;
    if (w >= N_NODES) return;
    int lane = threadIdx.x & 31;
    const float4* xin = (const float4*)in;
    float4 acc = xin[(size_t)w * 32 + lane];
    int e = g_off[w];
    int end = g_off[w + 1];
    for (; e + 4 <= end; e += 4) {
        int s0 = g_csr[e], s1 = g_csr[e + 1], s2 = g_csr[e + 2], s3 = g_csr[e + 3];
        float4 v0 = xin[(size_t)s0 * 32 + lane];
        float4 v1 = xin[(size_t)s1 * 32 + lane];
        float4 v2 = xin[(size_t)s2 * 32 + lane];
        float4 v3 = xin[(size_t)s3 * 32 + lane];
        acc.x += (v0.x + v1.x) + (v2.x + v3.x);
        acc.y += (v0.y + v1.y) + (v2.y + v3.y);
        acc.z += (v0.z + v1.z) + (v2.z + v3.z);
        acc.w += (v0.w + v1.w) + (v2.w + v3.w);
    }
    for (; e < end; e++) {
        int s0 = g_csr[e];
        float4 v0 = xin[(size_t)s0 * 32 + lane];
        acc.x += v0.x; acc.y += v0.y; acc.z += v0.z; acc.w += v0.w;
    }
    ((float4*)g_t)[(size_t)w * 32 + lane] = acc;
}

// ---------------- GEMM with packed f32x2 FMAs --------------------------------
// block: 64 nodes x 128 cols, 256 threads, thread tile 8 nodes x 4 cols.
// Accumulators are f32x2 pairs holding (sum over even k, sum over odd k).
__global__ void __launch_bounds__(256, 2)
k_gemm(const float* __restrict__ W, const float* __restrict__ b,
       int src_sel, int dst_sel, int do_relu) {
    extern __shared__ float smem[];
    float* sW = smem;            // 128*128 floats (row k, col j)
    float* sT = smem + F * F;    // 64*128 floats

    const float* in = src_sel ? (const float*)g_m : (const float*)g_t;
    float* out = dst_sel ? (float*)g_h : (float*)g_m;

    int tid = threadIdx.x;
    int nbase = blockIdx.x * 64;

    const float4* W4 = (const float4*)W;
    float4* sW4 = (float4*)sW;
    #pragma unroll
    for (int i = 0; i < 16; i++) sW4[tid + i * 256] = W4[tid + i * 256];

    const float4* T4 = (const float4*)in;
    float4* sT4 = (float4*)sT;
    #pragma unroll
    for (int i = 0; i < 8; i++) {
        int idx = tid + i * 256;          // float4 index in 64x32 tile
        int n = nbase + (idx >> 5);
        sT4[idx] = (n < N_NODES) ? T4[(size_t)n * 32 + (idx & 31)]
                                 : make_float4(0.f, 0.f, 0.f, 0.f);
    }
    __syncthreads();

    int tx = tid & 31;   // cols tx*4 .. tx*4+3
    int ty = tid >> 5;   // nodes ty*8 .. ty*8+7

    unsigned long long acc[8][4];
    #pragma unroll
    for (int i = 0; i < 8; i++)
        #pragma unroll
        for (int j = 0; j < 4; j++) acc[i][j] = 0ULL;

    const float* tb = sT + (ty * 8) * F;
    const float* wb = sW + tx * 4;

    #pragma unroll 4
    for (int k = 0; k < F; k += 2) {
        float4 wa = *(const float4*)(wb + k * F);
        float4 wc = *(const float4*)(wb + (k + 1) * F);
        unsigned long long w0 = pk2(wa.x, wc.x);
        unsigned long long w1 = pk2(wa.y, wc.y);
        unsigned long long w2 = pk2(wa.z, wc.z);
        unsigned long long w3 = pk2(wa.w, wc.w);
        #pragma unroll
        for (int i = 0; i < 8; i++) {
            unsigned long long t2 = *(const unsigned long long*)(tb + i * F + k);
            fma2(acc[i][0], t2, w0);
            fma2(acc[i][1], t2, w1);
            fma2(acc[i][2], t2, w2);
            fma2(acc[i][3], t2, w3);
        }
    }

    float4 bv = *(const float4*)(b + tx * 4);
    #pragma unroll
    for (int i = 0; i < 8; i++) {
        int n = nbase + ty * 8 + i;
        if (n < N_NODES) {
            float4 o;
            o.x = fold2(acc[i][0]) + bv.x;
            o.y = fold2(acc[i][1]) + bv.y;
            o.z = fold2(acc[i][2]) + bv.z;
            o.w = fold2(acc[i][3]) + bv.w;
            if (do_relu) {
                o.x = fmaxf(o.x, 0.f); o.y = fmaxf(o.y, 0.f);
                o.z = fmaxf(o.z, 0.f); o.w = fmaxf(o.w, 0.f);
            }
            *(float4*)(out + (size_t)n * F + tx * 4) = o;
        }
    }
}

// ---------------- final 128 -> 1 dot per node --------------------------------
__global__ void k_dot(const float* __restrict__ w, const float* __restrict__ b,
                      float* __restrict__ out) {
    __shared__ __align__(16) float sw[F];
    if (threadIdx.x < F) sw[threadIdx.x] = w[threadIdx.x];
    __syncthreads();
    int node = (blockIdx.x * blockDim.x + threadIdx.x) >> 5;
    if (node >= N_NODES) return;
    int lane = threadIdx.x & 31;
    float4 v = ((const float4*)g_m)[(size_t)node * 32 + lane];
    float4 wv = ((const float4*)sw)[lane];
    float s = v.x * wv.x + v.y * wv.y + v.z * wv.z + v.w * wv.w;
    #pragma unroll
    for (int o = 16; o; o >>= 1) s += __shfl_down_sync(0xffffffffu, s, o);
    if (lane == 0) out[node] = s + b[0];
}

// ---------------- launch ------------------------------------------------------
extern "C" void kernel_launch(void* const* d_in, const int* in_sizes, int n_in,
                              void* d_out, int out_size) {
    const float* x = (const float*)d_in[0];
    const void* ei = d_in[1];
    const float* w11 = (const float*)d_in[2];
    const float* b11 = (const float*)d_in[3];
    const float* w12 = (const float*)d_in[4];
    const float* b12 = (const float*)d_in[5];
    const float* w21 = (const float*)d_in[6];
    const float* b21 = (const float*)d_in[7];
    const float* w22 = (const float*)d_in[8];
    const float* b22 = (const float*)d_in[9];
    const float* w31 = (const float*)d_in[10];
    const float* b31 = (const float*)d_in[11];
    const float* w32 = (const float*)d_in[12];
    const float* b32 = (const float*)d_in[13];
    float* out = (float*)d_out;

    static int smem_set = 0;
    const int SMEM = (F * F + 64 * F) * (int)sizeof(float); // 96 KB
    if (!smem_set) {
        cudaFuncSetAttribute(k_gemm, cudaFuncAttributeMaxDynamicSharedMemorySize, SMEM);
        smem_set = 1;
    }

    // CSR build (depends only on edge_index)
    k_detect<<<1, 1024>>>((const unsigned int*)ei);
    k_zero_off<<<(N_NODES + 256) / 256, 256>>>();
    k_count<<<(N_EDGES + 255) / 256, 256>>>(ei);
    k_scan1<<<SCAN_B, 512>>>();
    k_scan2<<<1, 256>>>();
    k_scan3<<<SCAN_B, 512>>>();
    k_fill<<<(N_EDGES + 255) / 256, 256>>>(ei);

    const int AGG_BLOCKS = (N_NODES * 32 + 255) / 256;   // warp per node
    const int GEMM_BLOCKS = (N_NODES + 63) / 64;

    const float* W1s[3] = {w11, w21, w31};
    const float* B1s[3] = {b11, b21, b31};
    const float* W2s[2] = {w12, w22};
    const float* B2s[2] = {b12, b22};

    for (int l = 0; l < 3; l++) {
        k_agg<<<AGG_BLOCKS, 256>>>(x, l);                            // -> g_t
        k_gemm<<<GEMM_BLOCKS, 256, SMEM>>>(W1s[l], B1s[l], 0, 0, 1); // g_t -> g_m (relu)
        if (l < 2) {
            k_gemm<<<GEMM_BLOCKS, 256, SMEM>>>(W2s[l], B2s[l], 1, 1, 0); // g_m -> g_h
        } else {
            k_dot<<<AGG_BLOCKS, 256>>>(w32, b32, out);               // g_m -> out
        }
    }
}